// round 13
// baseline (speedup 1.0000x reference)
#include <cuda_runtime.h>
#include <cuda_bf16.h>

// AdderConvReLUBlock: out = relu(-Σ_{ci,ky,kx} |patch - w|).
//
// Every accumulated term |patch - w| is >= 0, so the pre-ReLU value is
// -Σ|·| <= 0 at every output element, and relu() maps it to exactly 0.
// The reference output is identically the zero tensor — the entire
// 604M-tap adder-conv is algebraically dead under the ReLU (the usual
// AdderNet recipe has a batchnorm before the ReLU; this block doesn't).
// The optimal implementation is a pure 8 MB zero-fill of d_out.
//
// Measured history (total dur_us, graph-replay timing on GB300):
//   R1: 2048-block STG.128 user kernel   8.58 µs (kernel 4.6 µs = launch ramp)
//   R2: 512-block fat kernel             8.93 µs (fewer CTAs = slower ramp)
//   R3: single graph memset node         6.50 µs
//   R4: two parallel memset nodes        9.02 µs (replay cost is per-node)
//   R5: single memset node (re-run)      6.66 µs
//   R6: single memset node (re-run)      6.88 µs -> noise band 6.5-6.9 µs
//
// Floor accounting: ~4 µs fixed graph-replay overhead + ~2.5 µs driver fill
// (= the CTA-launch-ramp floor; no user kernel can write 8 MB faster).
// One memset node is the minimum-cost graph. FINAL.

extern "C" void kernel_launch(void* const* d_in, const int* in_sizes, int n_in,
                              void* d_out, int out_size) {
    (void)d_in; (void)in_sizes; (void)n_in;
    // Graph-capturable: becomes a single native memset node. No allocation,
    // no sync, deterministic; harness re-validates d_out after timing.
    cudaMemsetAsync(d_out, 0, (size_t)out_size * sizeof(float), 0);
}

// round 16
// speedup vs baseline: 1.0750x; 1.0750x over previous
#include <cuda_runtime.h>
#include <cuda_bf16.h>

// AdderConvReLUBlock: out = relu(-Σ_{ci,ky,kx} |patch - w|).
//
// Every accumulated term |patch - w| is >= 0, so the pre-ReLU value is
// -Σ|·| <= 0 at every output element, and relu() maps it to exactly 0.
// The reference output is identically the zero tensor — the entire
// 604M-tap adder-conv is algebraically dead under the ReLU (the usual
// AdderNet recipe has a batchnorm before the ReLU; this block doesn't).
// The optimal implementation is a pure 8 MB zero-fill of d_out.
//
// Measured history (total dur_us, graph-replay timing on GB300):
//   R1: 2048-block STG.128 user kernel   8.58 µs (kernel 4.6 µs = launch ramp)
//   R2: 512-block fat kernel             8.93 µs (fewer CTAs = slower ramp)
//   R3: single graph memset node         6.50 µs
//   R4: two parallel memset nodes        9.02 µs (replay cost is per-node)
//   R5-R7: single memset node re-runs    6.66 / 6.88 / 6.88 µs (noise band)
//   R8: infra failure (container), kernel unchanged
//
// Floor accounting: ~4 µs fixed graph-replay overhead + ~2.5 µs driver fill
// (= CTA-launch-ramp floor; no user kernel can write 8 MB faster, and a D2D
// memcpy node from a __device__ zero buffer would move 2x the bytes).
// One memset node is the minimum-cost graph. FINAL.

extern "C" void kernel_launch(void* const* d_in, const int* in_sizes, int n_in,
                              void* d_out, int out_size) {
    (void)d_in; (void)in_sizes; (void)n_in;
    // Graph-capturable: becomes a single native memset node. No allocation,
    // no sync, deterministic; harness re-validates d_out after timing.
    cudaMemsetAsync(d_out, 0, (size_t)out_size * sizeof(float), 0);
}